// round 1
// baseline (speedup 1.0000x reference)
#include <cuda_runtime.h>
#include <cuda_bf16.h>
#include <math.h>

#define N_NODES 50000
#define N_EDGES 800000
#define IN_F 256
#define HID 128
#define OUT_F 8
#define N_GRAPHS 256
#define NEG_SLOPE 0.2f

// ---------------- scratch (static device globals; no runtime alloc) ----------
__device__ int   g_is64;
__device__ int   g_src[N_EDGES];
__device__ int   g_dstv[N_EDGES];
__device__ int   g_batch[N_NODES];
__device__ int   g_deg[N_NODES];
__device__ int   g_rowptr[N_NODES + 1];
__device__ int   g_cursor[N_NODES];
__device__ int   g_csrc[N_EDGES];          // edge sources sorted by dst
__device__ float g_h[N_NODES * HID];       // GEMM output (per layer)
__device__ float g_out[N_NODES * HID];     // aggregation output / next input
__device__ float g_as[N_NODES];
__device__ float g_ad[N_NODES];
__device__ float g_pool[N_GRAPHS * HID];
__device__ int   g_cnt[N_GRAPHS];

// ---------------- utility kernels -------------------------------------------
__global__ void zero_f(float* p, int n) {
    int i = blockIdx.x * blockDim.x + threadIdx.x;
    if (i < n) p[i] = 0.0f;
}
__global__ void zero_i(int* p, int n) {
    int i = blockIdx.x * blockDim.x + threadIdx.x;
    if (i < n) p[i] = 0;
}

// Detect whether edge_index buffer is int64 (high words of values < 2^31 are 0)
__global__ void detect_kernel(const unsigned* buf) {
    if (threadIdx.x == 0 && blockIdx.x == 0) {
        int is64 = 1;
        for (int i = 0; i < 256; i++) {
            if (buf[2 * (i * 3001) + 1] != 0u) { is64 = 0; break; }
        }
        g_is64 = is64;
    }
}

__global__ void convert_edges(const void* buf, int E) {
    int e = blockIdx.x * blockDim.x + threadIdx.x;
    if (e >= E) return;
    if (g_is64) {
        const long long* p = (const long long*)buf;
        g_src[e]  = (int)p[e];
        g_dstv[e] = (int)p[E + e];
    } else {
        const int* p = (const int*)buf;
        g_src[e]  = p[e];
        g_dstv[e] = p[E + e];
    }
}

__global__ void convert_batch(const void* buf, int n) {
    int i = blockIdx.x * blockDim.x + threadIdx.x;
    if (i >= n) return;
    if (g_is64) g_batch[i] = (int)((const long long*)buf)[i];
    else        g_batch[i] = ((const int*)buf)[i];
}

// ---------------- CSR construction ------------------------------------------
__global__ void hist_kernel(int E) {
    int e = blockIdx.x * blockDim.x + threadIdx.x;
    if (e < E) atomicAdd(&g_deg[g_dstv[e]], 1);
}

// Single-block exclusive scan over g_deg -> g_rowptr, g_cursor
__global__ void scan_kernel() {
    __shared__ int sh[1024];
    __shared__ int carry_sh;
    int tid = threadIdx.x;
    if (tid == 0) carry_sh = 0;
    __syncthreads();
    for (int base = 0; base < N_NODES; base += 1024) {
        int idx = base + tid;
        int v = (idx < N_NODES) ? g_deg[idx] : 0;
        sh[tid] = v;
        __syncthreads();
        for (int off = 1; off < 1024; off <<= 1) {
            int t = (tid >= off) ? sh[tid - off] : 0;
            __syncthreads();
            sh[tid] += t;
            __syncthreads();
        }
        int carry = carry_sh;
        if (idx < N_NODES) {
            int excl = carry + sh[tid] - v;
            g_rowptr[idx] = excl;
            g_cursor[idx] = excl;
        }
        __syncthreads();
        if (tid == 1023) carry_sh = carry + sh[1023];
        __syncthreads();
    }
    if (tid == 0) g_rowptr[N_NODES] = carry_sh;
}

__global__ void scatter_kernel(int E) {
    int e = blockIdx.x * blockDim.x + threadIdx.x;
    if (e >= E) return;
    int d = g_dstv[e];
    int pos = atomicAdd(&g_cursor[d], 1);
    g_csrc[pos] = g_src[e];
}

// ---------------- GEMM: C[M,128] = A[M,K] @ W[K,128] -------------------------
#define BM 128
#define BN 128
#define BK 16
__global__ __launch_bounds__(256) void gemm_kernel(
    const float* __restrict__ A, const float* __restrict__ W,
    float* __restrict__ C, int M, int K)
{
    __shared__ float As[BK][BM + 4];
    __shared__ float Bs[BK][BN + 4];
    int block_row = blockIdx.x * BM;
    int tid = threadIdx.x;
    int tx = tid & 15, ty = tid >> 4;

    float acc[8][8];
#pragma unroll
    for (int i = 0; i < 8; i++)
#pragma unroll
        for (int j = 0; j < 8; j++) acc[i][j] = 0.0f;

    for (int k0 = 0; k0 < K; k0 += BK) {
        // A tile: 128 rows x 16 cols, float4 loads (2 per thread)
#pragma unroll
        for (int i = 0; i < 2; i++) {
            int idx = tid * 2 + i;            // 0..511
            int m = idx >> 2, k4 = (idx & 3) * 4;
            int gm = block_row + m;
            float4 v = make_float4(0, 0, 0, 0);
            if (gm < M) v = *(const float4*)&A[(long)gm * K + k0 + k4];
            As[k4 + 0][m] = v.x; As[k4 + 1][m] = v.y;
            As[k4 + 2][m] = v.z; As[k4 + 3][m] = v.w;
        }
        // W tile: 16 rows x 128 cols
#pragma unroll
        for (int i = 0; i < 2; i++) {
            int idx = tid * 2 + i;
            int k = idx >> 5, c4 = (idx & 31) * 4;
            float4 v = *(const float4*)&W[(k0 + k) * 128 + c4];
            Bs[k][c4 + 0] = v.x; Bs[k][c4 + 1] = v.y;
            Bs[k][c4 + 2] = v.z; Bs[k][c4 + 3] = v.w;
        }
        __syncthreads();
#pragma unroll
        for (int kk = 0; kk < BK; kk++) {
            float a[8], b[8];
#pragma unroll
            for (int i = 0; i < 8; i++) a[i] = As[kk][ty * 8 + i];
#pragma unroll
            for (int j = 0; j < 8; j++) b[j] = Bs[kk][tx * 8 + j];
#pragma unroll
            for (int i = 0; i < 8; i++)
#pragma unroll
                for (int j = 0; j < 8; j++) acc[i][j] = fmaf(a[i], b[j], acc[i][j]);
        }
        __syncthreads();
    }
#pragma unroll
    for (int i = 0; i < 8; i++) {
        int gm = block_row + ty * 8 + i;
        if (gm < M) {
#pragma unroll
            for (int j = 0; j < 8; j += 4) {
                float4 v = make_float4(acc[i][j], acc[i][j + 1], acc[i][j + 2], acc[i][j + 3]);
                *(float4*)&C[(long)gm * 128 + tx * 8 + j] = v;
            }
        }
    }
}

// ---------------- per-node attention coefficients ----------------------------
__global__ void alpha_kernel(const float* __restrict__ H,
                             const float* __restrict__ a_src,
                             const float* __restrict__ a_dst)
{
    int warp = (blockIdx.x * blockDim.x + threadIdx.x) >> 5;
    int lane = threadIdx.x & 31;
    if (warp >= N_NODES) return;
    float4 h = *(const float4*)&H[(long)warp * 128 + lane * 4];
    float4 s = *(const float4*)&a_src[lane * 4];
    float4 d = *(const float4*)&a_dst[lane * 4];
    float ps = h.x * s.x + h.y * s.y + h.z * s.z + h.w * s.w;
    float pd = h.x * d.x + h.y * d.y + h.z * d.z + h.w * d.w;
#pragma unroll
    for (int o = 16; o; o >>= 1) {
        ps += __shfl_xor_sync(0xffffffffu, ps, o);
        pd += __shfl_xor_sync(0xffffffffu, pd, o);
    }
    if (lane == 0) { g_as[warp] = ps; g_ad[warp] = pd; }
}

// ---------------- edge aggregation (warp per destination node) ---------------
__device__ __forceinline__ float lrelu(float x) {
    return x > 0.0f ? x : NEG_SLOPE * x;
}

__global__ __launch_bounds__(256) void agg_kernel(
    const float* __restrict__ H, const float* __restrict__ bias,
    float* __restrict__ Out, int do_relu)
{
    int warp = (blockIdx.x * blockDim.x + threadIdx.x) >> 5;
    int lane = threadIdx.x & 31;
    if (warp >= N_NODES) return;
    int beg = g_rowptr[warp], end = g_rowptr[warp + 1];
    float ad = g_ad[warp];

    // pass 1: max logit
    float m = -INFINITY;
    for (int i = beg + lane; i < end; i += 32)
        m = fmaxf(m, lrelu(g_as[g_csrc[i]] + ad));
#pragma unroll
    for (int o = 16; o; o >>= 1) m = fmaxf(m, __shfl_xor_sync(0xffffffffu, m, o));

    // pass 2: sum of exp
    float s = 0.0f;
    for (int i = beg + lane; i < end; i += 32)
        s += __expf(lrelu(g_as[g_csrc[i]] + ad) - m);
#pragma unroll
    for (int o = 16; o; o >>= 1) s += __shfl_xor_sync(0xffffffffu, s, o);
    float inv = (end > beg) ? 1.0f / s : 0.0f;

    // pass 3: weighted feature accumulation (full-warp coalesced row loads)
    float4 acc = make_float4(0, 0, 0, 0);
    for (int i = beg; i < end; i++) {
        int src = g_csrc[i];
        float w = __expf(lrelu(g_as[src] + ad) - m) * inv;
        float4 hv = *(const float4*)&H[(long)src * 128 + lane * 4];
        acc.x = fmaf(w, hv.x, acc.x);
        acc.y = fmaf(w, hv.y, acc.y);
        acc.z = fmaf(w, hv.z, acc.z);
        acc.w = fmaf(w, hv.w, acc.w);
    }
    float4 bv = *(const float4*)&bias[lane * 4];
    acc.x += bv.x; acc.y += bv.y; acc.z += bv.z; acc.w += bv.w;
    if (do_relu) {
        acc.x = fmaxf(acc.x, 0.0f); acc.y = fmaxf(acc.y, 0.0f);
        acc.z = fmaxf(acc.z, 0.0f); acc.w = fmaxf(acc.w, 0.0f);
    }
    *(float4*)&Out[(long)warp * 128 + lane * 4] = acc;
}

// ---------------- pooling (batch is sorted -> run-length segmented) ----------
#define NODES_PER_BLOCK 64
__global__ void pool_kernel(const float* __restrict__ H) {
    int tid = threadIdx.x;   // 128 = channel
    int n0 = blockIdx.x * NODES_PER_BLOCK;
    if (n0 >= N_NODES) return;
    int n1 = min(n0 + NODES_PER_BLOCK, N_NODES);
    int cur = g_batch[n0];
    float acc = 0.0f;
    int run = 0;
    for (int n = n0; n < n1; n++) {
        int g = g_batch[n];
        if (g != cur) {
            atomicAdd(&g_pool[cur * 128 + tid], acc);
            if (tid == 0) atomicAdd(&g_cnt[cur], run);
            acc = 0.0f; run = 0; cur = g;
        }
        acc += H[(long)n * 128 + tid];
        run++;
    }
    atomicAdd(&g_pool[cur * 128 + tid], acc);
    if (tid == 0) atomicAdd(&g_cnt[cur], run);
}

// ---------------- final linear ----------------------------------------------
__global__ void final_kernel(const float* __restrict__ lin_w,
                             const float* __restrict__ lin_b,
                             float* __restrict__ out)
{
    int t = blockIdx.x * blockDim.x + threadIdx.x;
    if (t >= N_GRAPHS * OUT_F) return;
    int g = t >> 3, o = t & 7;
    float c = fmaxf((float)g_cnt[g], 1.0f);
    float invc = 1.0f / c;
    float acc = 0.0f;
    for (int k = 0; k < 128; k++)
        acc = fmaf(g_pool[g * 128 + k] * invc, lin_w[k * OUT_F + o], acc);
    out[t] = acc + lin_b[o];
}

// ---------------- driver -----------------------------------------------------
extern "C" void kernel_launch(void* const* d_in, const int* in_sizes, int n_in,
                              void* d_out, int out_size)
{
    const float* x      = (const float*)d_in[0];
    const void*  eidx   = d_in[1];
    const void*  batch  = d_in[3];
    const float* W[3]     = {(const float*)d_in[4],  (const float*)d_in[8],  (const float*)d_in[12]};
    const float* a_src[3] = {(const float*)d_in[5],  (const float*)d_in[9],  (const float*)d_in[13]};
    const float* a_dst[3] = {(const float*)d_in[6],  (const float*)d_in[10], (const float*)d_in[14]};
    const float* bias[3]  = {(const float*)d_in[7],  (const float*)d_in[11], (const float*)d_in[15]};
    const float* lin_w  = (const float*)d_in[16];
    const float* lin_b  = (const float*)d_in[17];
    float* out = (float*)d_out;

    const int E = N_EDGES;
    const int eb = (E + 255) / 256;
    const int nb = (N_NODES + 255) / 256;

    // dtype detection + index conversion
    detect_kernel<<<1, 32>>>((const unsigned*)eidx);
    convert_edges<<<eb, 256>>>(eidx, E);
    convert_batch<<<nb, 256>>>(batch, N_NODES);

    // CSR by destination
    {
        int* degp; cudaGetSymbolAddress((void**)&degp, g_deg);
        zero_i<<<nb, 256>>>(degp, N_NODES);
    }
    hist_kernel<<<eb, 256>>>(E);
    scan_kernel<<<1, 1024>>>();
    scatter_kernel<<<eb, 256>>>(E);

    float* hbuf;  cudaGetSymbolAddress((void**)&hbuf, g_h);
    float* obuf;  cudaGetSymbolAddress((void**)&obuf, g_out);
    float* poolp; cudaGetSymbolAddress((void**)&poolp, g_pool);
    int*   cntp;  cudaGetSymbolAddress((void**)&cntp, g_cnt);

    const int gemm_blocks = (N_NODES + BM - 1) / BM;
    const int warp_blocks = (N_NODES * 32 + 255) / 256;

    // layer 0 (input x, K=256)
    gemm_kernel<<<gemm_blocks, 256>>>(x, W[0], hbuf, N_NODES, IN_F);
    alpha_kernel<<<warp_blocks, 256>>>(hbuf, a_src[0], a_dst[0]);
    agg_kernel<<<warp_blocks, 256>>>(hbuf, bias[0], obuf, 1);

    // layers 1,2 (K=128)
    for (int l = 1; l < 3; l++) {
        gemm_kernel<<<gemm_blocks, 256>>>(obuf, W[l], hbuf, N_NODES, HID);
        alpha_kernel<<<warp_blocks, 256>>>(hbuf, a_src[l], a_dst[l]);
        agg_kernel<<<warp_blocks, 256>>>(hbuf, bias[l], obuf, l == 2 ? 0 : 1);
    }

    // pooling + final linear
    zero_f<<<(N_GRAPHS * 128 + 255) / 256, 256>>>(poolp, N_GRAPHS * 128);
    zero_i<<<1, 256>>>(cntp, N_GRAPHS);
    pool_kernel<<<(N_NODES + NODES_PER_BLOCK - 1) / NODES_PER_BLOCK, 128>>>(obuf);
    final_kernel<<<(N_GRAPHS * OUT_F + 255) / 256, 256>>>(lin_w, lin_b, out);
}

// round 2
// speedup vs baseline: 1.3590x; 1.3590x over previous
#include <cuda_runtime.h>
#include <cuda_bf16.h>
#include <math.h>
#include <stdint.h>

#define N_NODES 50000
#define N_EDGES 800000
#define IN_F 256
#define HID 128
#define OUT_F 8
#define N_GRAPHS 256
#define NEG_SLOPE 0.2f

// ---------------- scratch (static device globals; no runtime alloc) ----------
__device__ int   g_is64;
__device__ int   g_src[N_EDGES];
__device__ int   g_dstv[N_EDGES];
__device__ int   g_batch[N_NODES];
__device__ int   g_deg[N_NODES];
__device__ int   g_rowptr[N_NODES + 1];
__device__ int   g_cursor[N_NODES];
__device__ int   g_csrc[N_EDGES];          // edge sources sorted by dst
__device__ int   g_bsum[64];
__device__ float g_h[N_NODES * HID];       // GEMM output (per layer)
__device__ float g_out[N_NODES * HID];     // aggregation output / next input
__device__ float g_as[N_NODES];
__device__ float g_ad[N_NODES];
__device__ float g_pool[N_GRAPHS * HID];
__device__ int   g_cnt[N_GRAPHS];

// ---------------- utility kernels -------------------------------------------
__global__ void zero_f(float* p, int n) {
    int i = blockIdx.x * blockDim.x + threadIdx.x;
    if (i < n) p[i] = 0.0f;
}
__global__ void zero_i(int* p, int n) {
    int i = blockIdx.x * blockDim.x + threadIdx.x;
    if (i < n) p[i] = 0;
}

// Detect whether edge_index buffer is int64 (high words of values < 2^31 are 0)
__global__ void detect_kernel(const unsigned* buf) {
    if (threadIdx.x == 0 && blockIdx.x == 0) {
        int is64 = 1;
        for (int i = 0; i < 256; i++) {
            if (buf[2 * (i * 3001) + 1] != 0u) { is64 = 0; break; }
        }
        g_is64 = is64;
    }
}

// convert + destination histogram in one pass (g_deg must be zeroed before)
__global__ void convert_edges(const void* buf, int E) {
    int e = blockIdx.x * blockDim.x + threadIdx.x;
    if (e >= E) return;
    int s, d;
    if (g_is64) {
        const long long* p = (const long long*)buf;
        s = (int)p[e];  d = (int)p[E + e];
    } else {
        const int* p = (const int*)buf;
        s = p[e];  d = p[E + e];
    }
    g_src[e] = s;
    g_dstv[e] = d;
    atomicAdd(&g_deg[d], 1);
}

__global__ void convert_batch(const void* buf, int n) {
    int i = blockIdx.x * blockDim.x + threadIdx.x;
    if (i >= n) return;
    if (g_is64) g_batch[i] = (int)((const long long*)buf)[i];
    else        g_batch[i] = ((const int*)buf)[i];
}

// ---------------- hierarchical CSR scan --------------------------------------
// scan1: per-1024-block inclusive scan -> exclusive prefixes (no global offset)
__global__ void scan1_kernel() {
    __shared__ int sh[1024];
    int b = blockIdx.x, tid = threadIdx.x;
    int idx = b * 1024 + tid;
    int v = (idx < N_NODES) ? g_deg[idx] : 0;
    sh[tid] = v;
    __syncthreads();
    for (int off = 1; off < 1024; off <<= 1) {
        int t = (tid >= off) ? sh[tid - off] : 0;
        __syncthreads();
        sh[tid] += t;
        __syncthreads();
    }
    if (idx < N_NODES) g_rowptr[idx] = sh[tid] - v;
    if (tid == 1023) g_bsum[b] = sh[1023];
}

#define N_SCAN_BLOCKS ((N_NODES + 1023) / 1024)   // 49
// scan2: scan the 49 block sums (single 64-thread block)
__global__ void scan2_kernel() {
    __shared__ int sh[64];
    int tid = threadIdx.x;
    int v = (tid < N_SCAN_BLOCKS) ? g_bsum[tid] : 0;
    sh[tid] = v;
    __syncthreads();
    for (int off = 1; off < 64; off <<= 1) {
        int t = (tid >= off) ? sh[tid - off] : 0;
        __syncthreads();
        sh[tid] += t;
        __syncthreads();
    }
    if (tid < N_SCAN_BLOCKS) g_bsum[tid] = sh[tid] - v;   // exclusive
    if (tid == N_SCAN_BLOCKS - 1) g_rowptr[N_NODES] = sh[tid];
}
// scan3: add block offsets, init cursor
__global__ void scan3_kernel() {
    int i = blockIdx.x * blockDim.x + threadIdx.x;
    if (i >= N_NODES) return;
    int r = g_rowptr[i] + g_bsum[i >> 10];
    g_rowptr[i] = r;
    g_cursor[i] = r;
}

__global__ void scatter_kernel(int E) {
    int e = blockIdx.x * blockDim.x + threadIdx.x;
    if (e >= E) return;
    int d = g_dstv[e];
    int pos = atomicAdd(&g_cursor[d], 1);
    g_csrc[pos] = g_src[e];
}

// ---------------- TF32 tensor-core GEMM: C[M,128] = A[M,K] @ W[K,128] --------
#define BM 128
#define BN 128
#define BK 32

__device__ __forceinline__ float to_tf32(float x) {
    uint32_t u;
    asm("cvt.rna.tf32.f32 %0, %1;" : "=r"(u) : "f"(x));
    return __uint_as_float(u);
}

__device__ __forceinline__ void mma_tf32(float c[4], const uint32_t a[4],
                                         uint32_t b0, uint32_t b1) {
    asm volatile(
        "mma.sync.aligned.m16n8k8.row.col.f32.tf32.tf32.f32 "
        "{%0,%1,%2,%3}, {%4,%5,%6,%7}, {%8,%9}, {%0,%1,%2,%3};\n"
        : "+f"(c[0]), "+f"(c[1]), "+f"(c[2]), "+f"(c[3])
        : "r"(a[0]), "r"(a[1]), "r"(a[2]), "r"(a[3]), "r"(b0), "r"(b1));
}

__global__ __launch_bounds__(256) void gemm_tf32_kernel(
    const float* __restrict__ A, const float* __restrict__ W,
    float* __restrict__ C, int M, int K)
{
    __shared__ float As[BM][BK + 4];      // stride 36 -> banks 4*row+k (conflict-free frags)
    __shared__ float Ws[BK][BN + 8];      // stride 136 -> banks 8*k+col (conflict-free frags)
    int tid = threadIdx.x;
    int lane = tid & 31, warp = tid >> 5;
    int warpRow = warp >> 1, warpCol = warp & 1;   // 4 x 2 warp grid, warp tile 32x64
    int block_row = blockIdx.x * BM;
    int g = lane >> 2, tg = lane & 3;

    float c[2][8][4];
#pragma unroll
    for (int mi = 0; mi < 2; mi++)
#pragma unroll
        for (int ni = 0; ni < 8; ni++)
#pragma unroll
            for (int r = 0; r < 4; r++) c[mi][ni][r] = 0.0f;

    for (int k0 = 0; k0 < K; k0 += BK) {
        // A tile: 128 rows x 32 cols (1024 float4, 4 per thread)
#pragma unroll
        for (int i = 0; i < 4; i++) {
            int q = tid + i * 256;
            int row = q >> 3, c4 = q & 7;
            int gm = block_row + row;
            float4 v = make_float4(0, 0, 0, 0);
            if (gm < M) v = *(const float4*)&A[(size_t)gm * K + k0 + c4 * 4];
            float* dst = &As[row][c4 * 4];
            dst[0] = to_tf32(v.x); dst[1] = to_tf32(v.y);
            dst[2] = to_tf32(v.z); dst[3] = to_tf32(v.w);
        }
        // W tile: 32 rows x 128 cols (1024 float4, 4 per thread)
#pragma unroll
        for (int i = 0; i < 4; i++) {
            int q = tid + i * 256;
            int k = q >> 5, c4 = q & 31;
            float4 v = *(const float4*)&W[(size_t)(k0 + k) * BN + c4 * 4];
            float* dst = &Ws[k][c4 * 4];
            dst[0] = to_tf32(v.x); dst[1] = to_tf32(v.y);
            dst[2] = to_tf32(v.z); dst[3] = to_tf32(v.w);
        }
        __syncthreads();
#pragma unroll
        for (int ks = 0; ks < BK; ks += 8) {
            uint32_t a[2][4];
#pragma unroll
            for (int mi = 0; mi < 2; mi++) {
                int r = warpRow * 32 + mi * 16;
                a[mi][0] = __float_as_uint(As[r + g][ks + tg]);
                a[mi][1] = __float_as_uint(As[r + 8 + g][ks + tg]);
                a[mi][2] = __float_as_uint(As[r + g][ks + tg + 4]);
                a[mi][3] = __float_as_uint(As[r + 8 + g][ks + tg + 4]);
            }
#pragma unroll
            for (int ni = 0; ni < 8; ni++) {
                int cb = warpCol * 64 + ni * 8 + g;
                uint32_t b0 = __float_as_uint(Ws[ks + tg][cb]);
                uint32_t b1 = __float_as_uint(Ws[ks + tg + 4][cb]);
                mma_tf32(c[0][ni], a[0], b0, b1);
                mma_tf32(c[1][ni], a[1], b0, b1);
            }
        }
        __syncthreads();
    }
    // epilogue
#pragma unroll
    for (int mi = 0; mi < 2; mi++) {
#pragma unroll
        for (int ni = 0; ni < 8; ni++) {
            int r0 = block_row + warpRow * 32 + mi * 16 + g;
            int col = warpCol * 64 + ni * 8 + tg * 2;
            if (r0 < M)
                *(float2*)&C[(size_t)r0 * 128 + col] = make_float2(c[mi][ni][0], c[mi][ni][1]);
            int r1 = r0 + 8;
            if (r1 < M)
                *(float2*)&C[(size_t)r1 * 128 + col] = make_float2(c[mi][ni][2], c[mi][ni][3]);
        }
    }
}

// ---------------- per-node attention coefficients ----------------------------
__global__ void alpha_kernel(const float* __restrict__ H,
                             const float* __restrict__ a_src,
                             const float* __restrict__ a_dst)
{
    int warp = (blockIdx.x * blockDim.x + threadIdx.x) >> 5;
    int lane = threadIdx.x & 31;
    if (warp >= N_NODES) return;
    float4 h = *(const float4*)&H[(size_t)warp * 128 + lane * 4];
    float4 s = *(const float4*)&a_src[lane * 4];
    float4 d = *(const float4*)&a_dst[lane * 4];
    float ps = h.x * s.x + h.y * s.y + h.z * s.z + h.w * s.w;
    float pd = h.x * d.x + h.y * d.y + h.z * d.z + h.w * d.w;
#pragma unroll
    for (int o = 16; o; o >>= 1) {
        ps += __shfl_xor_sync(0xffffffffu, ps, o);
        pd += __shfl_xor_sync(0xffffffffu, pd, o);
    }
    if (lane == 0) { g_as[warp] = ps; g_ad[warp] = pd; }
}

// ---------------- edge aggregation (warp per destination node) ---------------
__device__ __forceinline__ float lrelu(float x) {
    return x > 0.0f ? x : NEG_SLOPE * x;
}

__global__ __launch_bounds__(256) void agg_kernel(
    const float* __restrict__ H, const float* __restrict__ bias,
    float* __restrict__ Out, int do_relu)
{
    int warp = (blockIdx.x * blockDim.x + threadIdx.x) >> 5;
    int lane = threadIdx.x & 31;
    if (warp >= N_NODES) return;
    int beg = g_rowptr[warp], end = g_rowptr[warp + 1];
    float ad = g_ad[warp];

    // pass 1: max logit
    float m = -INFINITY;
    for (int i = beg + lane; i < end; i += 32)
        m = fmaxf(m, lrelu(g_as[g_csrc[i]] + ad));
#pragma unroll
    for (int o = 16; o; o >>= 1) m = fmaxf(m, __shfl_xor_sync(0xffffffffu, m, o));

    // pass 2: sum of exp
    float s = 0.0f;
    for (int i = beg + lane; i < end; i += 32)
        s += __expf(lrelu(g_as[g_csrc[i]] + ad) - m);
#pragma unroll
    for (int o = 16; o; o >>= 1) s += __shfl_xor_sync(0xffffffffu, s, o);
    float inv = (end > beg) ? 1.0f / s : 0.0f;

    // pass 3: weighted feature accumulation, unroll x2 for MLP
    float4 acc0 = make_float4(0, 0, 0, 0);
    float4 acc1 = make_float4(0, 0, 0, 0);
    int i = beg;
    for (; i + 1 < end; i += 2) {
        int s0 = g_csrc[i], s1 = g_csrc[i + 1];
        float w0 = __expf(lrelu(g_as[s0] + ad) - m) * inv;
        float w1 = __expf(lrelu(g_as[s1] + ad) - m) * inv;
        float4 h0 = *(const float4*)&H[(size_t)s0 * 128 + lane * 4];
        float4 h1 = *(const float4*)&H[(size_t)s1 * 128 + lane * 4];
        acc0.x = fmaf(w0, h0.x, acc0.x); acc0.y = fmaf(w0, h0.y, acc0.y);
        acc0.z = fmaf(w0, h0.z, acc0.z); acc0.w = fmaf(w0, h0.w, acc0.w);
        acc1.x = fmaf(w1, h1.x, acc1.x); acc1.y = fmaf(w1, h1.y, acc1.y);
        acc1.z = fmaf(w1, h1.z, acc1.z); acc1.w = fmaf(w1, h1.w, acc1.w);
    }
    if (i < end) {
        int s0 = g_csrc[i];
        float w0 = __expf(lrelu(g_as[s0] + ad) - m) * inv;
        float4 h0 = *(const float4*)&H[(size_t)s0 * 128 + lane * 4];
        acc0.x = fmaf(w0, h0.x, acc0.x); acc0.y = fmaf(w0, h0.y, acc0.y);
        acc0.z = fmaf(w0, h0.z, acc0.z); acc0.w = fmaf(w0, h0.w, acc0.w);
    }
    float4 acc = make_float4(acc0.x + acc1.x, acc0.y + acc1.y,
                             acc0.z + acc1.z, acc0.w + acc1.w);
    float4 bv = *(const float4*)&bias[lane * 4];
    acc.x += bv.x; acc.y += bv.y; acc.z += bv.z; acc.w += bv.w;
    if (do_relu) {
        acc.x = fmaxf(acc.x, 0.0f); acc.y = fmaxf(acc.y, 0.0f);
        acc.z = fmaxf(acc.z, 0.0f); acc.w = fmaxf(acc.w, 0.0f);
    }
    *(float4*)&Out[(size_t)warp * 128 + lane * 4] = acc;
}

// ---------------- pooling (batch is sorted -> run-length segmented) ----------
#define NODES_PER_BLOCK 64
__global__ void pool_kernel(const float* __restrict__ H) {
    int tid = threadIdx.x;   // 128 = channel
    int n0 = blockIdx.x * NODES_PER_BLOCK;
    if (n0 >= N_NODES) return;
    int n1 = min(n0 + NODES_PER_BLOCK, N_NODES);
    int cur = g_batch[n0];
    float acc = 0.0f;
    int run = 0;
    for (int n = n0; n < n1; n++) {
        int gg = g_batch[n];
        if (gg != cur) {
            atomicAdd(&g_pool[cur * 128 + tid], acc);
            if (tid == 0) atomicAdd(&g_cnt[cur], run);
            acc = 0.0f; run = 0; cur = gg;
        }
        acc += H[(size_t)n * 128 + tid];
        run++;
    }
    atomicAdd(&g_pool[cur * 128 + tid], acc);
    if (tid == 0) atomicAdd(&g_cnt[cur], run);
}

// ---------------- final linear ----------------------------------------------
__global__ void final_kernel(const float* __restrict__ lin_w,
                             const float* __restrict__ lin_b,
                             float* __restrict__ out)
{
    int t = blockIdx.x * blockDim.x + threadIdx.x;
    if (t >= N_GRAPHS * OUT_F) return;
    int gg = t >> 3, o = t & 7;
    float cval = fmaxf((float)g_cnt[gg], 1.0f);
    float invc = 1.0f / cval;
    float acc = 0.0f;
    for (int k = 0; k < 128; k++)
        acc = fmaf(g_pool[gg * 128 + k] * invc, lin_w[k * OUT_F + o], acc);
    out[t] = acc + lin_b[o];
}

// ---------------- driver -----------------------------------------------------
extern "C" void kernel_launch(void* const* d_in, const int* in_sizes, int n_in,
                              void* d_out, int out_size)
{
    const float* x      = (const float*)d_in[0];
    const void*  eidx   = d_in[1];
    const void*  batch  = d_in[3];
    const float* W[3]     = {(const float*)d_in[4],  (const float*)d_in[8],  (const float*)d_in[12]};
    const float* a_src[3] = {(const float*)d_in[5],  (const float*)d_in[9],  (const float*)d_in[13]};
    const float* a_dst[3] = {(const float*)d_in[6],  (const float*)d_in[10], (const float*)d_in[14]};
    const float* bias[3]  = {(const float*)d_in[7],  (const float*)d_in[11], (const float*)d_in[15]};
    const float* lin_w  = (const float*)d_in[16];
    const float* lin_b  = (const float*)d_in[17];
    float* out = (float*)d_out;

    const int E = N_EDGES;
    const int eb = (E + 255) / 256;
    const int nb = (N_NODES + 255) / 256;

    int* degp; cudaGetSymbolAddress((void**)&degp, g_deg);
    float* hbuf;  cudaGetSymbolAddress((void**)&hbuf, g_h);
    float* obuf;  cudaGetSymbolAddress((void**)&obuf, g_out);
    float* poolp; cudaGetSymbolAddress((void**)&poolp, g_pool);
    int*   cntp;  cudaGetSymbolAddress((void**)&cntp, g_cnt);

    // dtype detection + index conversion + degree histogram
    detect_kernel<<<1, 32>>>((const unsigned*)eidx);
    zero_i<<<nb, 256>>>(degp, N_NODES);
    convert_edges<<<eb, 256>>>(eidx, E);
    convert_batch<<<nb, 256>>>(batch, N_NODES);

    // CSR by destination (hierarchical scan)
    scan1_kernel<<<N_SCAN_BLOCKS, 1024>>>();
    scan2_kernel<<<1, 64>>>();
    scan3_kernel<<<nb, 256>>>();
    scatter_kernel<<<eb, 256>>>(E);

    const int gemm_blocks = (N_NODES + BM - 1) / BM;
    const int warp_blocks = (N_NODES * 32 + 255) / 256;

    // layer 0 (input x, K=256)
    gemm_tf32_kernel<<<gemm_blocks, 256>>>(x, W[0], hbuf, N_NODES, IN_F);
    alpha_kernel<<<warp_blocks, 256>>>(hbuf, a_src[0], a_dst[0]);
    agg_kernel<<<warp_blocks, 256>>>(hbuf, bias[0], obuf, 1);

    // layers 1,2 (K=128)
    for (int l = 1; l < 3; l++) {
        gemm_tf32_kernel<<<gemm_blocks, 256>>>(obuf, W[l], hbuf, N_NODES, HID);
        alpha_kernel<<<warp_blocks, 256>>>(hbuf, a_src[l], a_dst[l]);
        agg_kernel<<<warp_blocks, 256>>>(hbuf, bias[l], obuf, l == 2 ? 0 : 1);
    }

    // pooling + final linear
    zero_f<<<(N_GRAPHS * 128 + 255) / 256, 256>>>(poolp, N_GRAPHS * 128);
    zero_i<<<1, 256>>>(cntp, N_GRAPHS);
    pool_kernel<<<(N_NODES + NODES_PER_BLOCK - 1) / NODES_PER_BLOCK, 128>>>(obuf);
    final_kernel<<<(N_GRAPHS * OUT_F + 255) / 256, 256>>>(lin_w, lin_b, out);
}

// round 5
// speedup vs baseline: 1.7670x; 1.3002x over previous
#include <cuda_runtime.h>
#include <cuda_fp16.h>
#include <math.h>
#include <stdint.h>

#define N_NODES 50000
#define N_EDGES 800000
#define IN_F 256
#define HID 128
#define OUT_F 8
#define N_GRAPHS 256
#define NEG_SLOPE 0.2f
#define NEG_BIG -1e30f

// ---------------- scratch (static device globals; no runtime alloc) ----------
__device__ int    g_is64;
__device__ int    g_src[N_EDGES];
__device__ int    g_dstv[N_EDGES];
__device__ int    g_deg[N_NODES];
__device__ int    g_rowptr[N_NODES + 1];
__device__ int    g_cursor[N_NODES];
__device__ int    g_csrc[N_EDGES];           // edge sources sorted by dst
__device__ int    g_bsum[64];
__device__ __half g_h[N_NODES * HID];        // GEMM output, fp16 (gather payload)
__device__ float  g_out[N_NODES * HID];      // aggregation output / next input
__device__ float  g_as[N_NODES];
__device__ float  g_ad[N_NODES];
__device__ float  g_pool[N_GRAPHS * HID];
__device__ int    g_cnt[N_GRAPHS];

// ---------------- utility kernels -------------------------------------------
__global__ void zero_i(int* p, int n) {
    int i = blockIdx.x * blockDim.x + threadIdx.x;
    if (i < n) p[i] = 0;
}
__global__ void zero_pool_kernel() {
    int i = blockIdx.x * blockDim.x + threadIdx.x;
    if (i < N_GRAPHS * HID) g_pool[i] = 0.0f;
    if (i < N_GRAPHS) g_cnt[i] = 0;
}

// Parallel int64-vs-int32 detection: all sampled high words zero => int64.
__global__ void detect_kernel(const unsigned* buf) {
    int i = threadIdx.x;                       // 256 threads
    int ok = (buf[2 * (i * 3001) + 1] == 0u) ? 1 : 0;
    int all = __syncthreads_and(ok);
    if (i == 0) g_is64 = all;
}

// convert + destination histogram in one pass (g_deg zeroed before)
__global__ void convert_edges(const void* buf, int E) {
    int e = blockIdx.x * blockDim.x + threadIdx.x;
    if (e >= E) return;
    int s, d;
    if (g_is64) {
        const long long* p = (const long long*)buf;
        s = (int)p[e];  d = (int)p[E + e];
    } else {
        const int* p = (const int*)buf;
        s = p[e];  d = p[E + e];
    }
    g_src[e] = s;
    g_dstv[e] = d;
    atomicAdd(&g_deg[d], 1);
}

// ---------------- hierarchical CSR scan --------------------------------------
__global__ void scan1_kernel() {
    __shared__ int sh[1024];
    int b = blockIdx.x, tid = threadIdx.x;
    int idx = b * 1024 + tid;
    int v = (idx < N_NODES) ? g_deg[idx] : 0;
    sh[tid] = v;
    __syncthreads();
    for (int off = 1; off < 1024; off <<= 1) {
        int t = (tid >= off) ? sh[tid - off] : 0;
        __syncthreads();
        sh[tid] += t;
        __syncthreads();
    }
    if (idx < N_NODES) g_rowptr[idx] = sh[tid] - v;
    if (tid == 1023) g_bsum[b] = sh[1023];
}

#define N_SCAN_BLOCKS ((N_NODES + 1023) / 1024)   // 49
__global__ void scan2_kernel() {
    __shared__ int sh[64];
    int tid = threadIdx.x;
    int v = (tid < N_SCAN_BLOCKS) ? g_bsum[tid] : 0;
    sh[tid] = v;
    __syncthreads();
    for (int off = 1; off < 64; off <<= 1) {
        int t = (tid >= off) ? sh[tid - off] : 0;
        __syncthreads();
        sh[tid] += t;
        __syncthreads();
    }
    if (tid < N_SCAN_BLOCKS) g_bsum[tid] = sh[tid] - v;   // exclusive
    if (tid == N_SCAN_BLOCKS - 1) g_rowptr[N_NODES] = sh[tid];
}
__global__ void scan3_kernel() {
    int i = blockIdx.x * blockDim.x + threadIdx.x;
    if (i >= N_NODES) return;
    int r = g_rowptr[i] + g_bsum[i >> 10];
    g_rowptr[i] = r;
    g_cursor[i] = r;
}

__global__ void scatter_kernel(int E) {
    int e = blockIdx.x * blockDim.x + threadIdx.x;
    if (e >= E) return;
    int d = g_dstv[e];
    int pos = atomicAdd(&g_cursor[d], 1);
    g_csrc[pos] = g_src[e];
}

// ---------------- TF32 tensor-core GEMM: H[M,128](fp16) = A[M,K] @ W[K,128] --
#define BM 128
#define BN 128
#define BK 32

__device__ __forceinline__ float to_tf32(float x) {
    uint32_t u;
    asm("cvt.rna.tf32.f32 %0, %1;" : "=r"(u) : "f"(x));
    return __uint_as_float(u);
}

__device__ __forceinline__ void mma_tf32(float c[4], const uint32_t a[4],
                                         uint32_t b0, uint32_t b1) {
    asm volatile(
        "mma.sync.aligned.m16n8k8.row.col.f32.tf32.tf32.f32 "
        "{%0,%1,%2,%3}, {%4,%5,%6,%7}, {%8,%9}, {%0,%1,%2,%3};\n"
        : "+f"(c[0]), "+f"(c[1]), "+f"(c[2]), "+f"(c[3])
        : "r"(a[0]), "r"(a[1]), "r"(a[2]), "r"(a[3]), "r"(b0), "r"(b1));
}

__global__ __launch_bounds__(256) void gemm_tf32_kernel(
    const float* __restrict__ A, const float* __restrict__ W,
    __half* __restrict__ C, int M, int K)
{
    __shared__ float As[BM][BK + 4];      // stride 36: conflict-free frag loads
    __shared__ float Ws[BK][BN + 8];      // stride 136: conflict-free frag loads
    int tid = threadIdx.x;
    int lane = tid & 31, warp = tid >> 5;
    int warpRow = warp >> 1, warpCol = warp & 1;   // 4 x 2 warps, warp tile 32x64
    int block_row = blockIdx.x * BM;
    int g = lane >> 2, tg = lane & 3;

    float c[2][8][4];
#pragma unroll
    for (int mi = 0; mi < 2; mi++)
#pragma unroll
        for (int ni = 0; ni < 8; ni++)
#pragma unroll
            for (int r = 0; r < 4; r++) c[mi][ni][r] = 0.0f;

    float4 aReg[4], wReg[4];

    // prefetch tile 0
#pragma unroll
    for (int i = 0; i < 4; i++) {
        int q = tid + i * 256;
        int row = q >> 3, c4 = q & 7;
        int gm = block_row + row;
        aReg[i] = make_float4(0, 0, 0, 0);
        if (gm < M) aReg[i] = *(const float4*)&A[(size_t)gm * K + c4 * 4];
        int k = q >> 5, c4w = q & 31;
        wReg[i] = *(const float4*)&W[(size_t)k * BN + c4w * 4];
    }

    for (int k0 = 0; k0 < K; k0 += BK) {
        // store prefetched tile into smem (tf32-converted)
#pragma unroll
        for (int i = 0; i < 4; i++) {
            int q = tid + i * 256;
            int row = q >> 3, c4 = q & 7;
            float* dst = &As[row][c4 * 4];
            dst[0] = to_tf32(aReg[i].x); dst[1] = to_tf32(aReg[i].y);
            dst[2] = to_tf32(aReg[i].z); dst[3] = to_tf32(aReg[i].w);
            int k = q >> 5, c4w = q & 31;
            float* dw = &Ws[k][c4w * 4];
            dw[0] = to_tf32(wReg[i].x); dw[1] = to_tf32(wReg[i].y);
            dw[2] = to_tf32(wReg[i].z); dw[3] = to_tf32(wReg[i].w);
        }
        __syncthreads();
        // prefetch next tile (overlaps MMA below)
        if (k0 + BK < K) {
#pragma unroll
            for (int i = 0; i < 4; i++) {
                int q = tid + i * 256;
                int row = q >> 3, c4 = q & 7;
                int gm = block_row + row;
                aReg[i] = make_float4(0, 0, 0, 0);
                if (gm < M) aReg[i] = *(const float4*)&A[(size_t)gm * K + k0 + BK + c4 * 4];
                int k = q >> 5, c4w = q & 31;
                wReg[i] = *(const float4*)&W[(size_t)(k0 + BK + k) * BN + c4w * 4];
            }
        }
#pragma unroll
        for (int ks = 0; ks < BK; ks += 8) {
            uint32_t a[2][4];
#pragma unroll
            for (int mi = 0; mi < 2; mi++) {
                int r = warpRow * 32 + mi * 16;
                a[mi][0] = __float_as_uint(As[r + g][ks + tg]);
                a[mi][1] = __float_as_uint(As[r + 8 + g][ks + tg]);
                a[mi][2] = __float_as_uint(As[r + g][ks + tg + 4]);
                a[mi][3] = __float_as_uint(As[r + 8 + g][ks + tg + 4]);
            }
#pragma unroll
            for (int ni = 0; ni < 8; ni++) {
                int cb = warpCol * 64 + ni * 8 + g;
                uint32_t b0 = __float_as_uint(Ws[ks + tg][cb]);
                uint32_t b1 = __float_as_uint(Ws[ks + tg + 4][cb]);
                mma_tf32(c[0][ni], a[0], b0, b1);
                mma_tf32(c[1][ni], a[1], b0, b1);
            }
        }
        __syncthreads();
    }
    // epilogue: fp16 output
#pragma unroll
    for (int mi = 0; mi < 2; mi++) {
#pragma unroll
        for (int ni = 0; ni < 8; ni++) {
            int r0 = block_row + warpRow * 32 + mi * 16 + g;
            int col = warpCol * 64 + ni * 8 + tg * 2;
            if (r0 < M)
                *(__half2*)&C[(size_t)r0 * 128 + col] =
                    __floats2half2_rn(c[mi][ni][0], c[mi][ni][1]);
            int r1 = r0 + 8;
            if (r1 < M)
                *(__half2*)&C[(size_t)r1 * 128 + col] =
                    __floats2half2_rn(c[mi][ni][2], c[mi][ni][3]);
        }
    }
}

// ---------------- per-node attention coefficients (fp16 H) -------------------
__global__ void alpha_kernel(const __half* __restrict__ H,
                             const float* __restrict__ a_src,
                             const float* __restrict__ a_dst)
{
    int warp = (blockIdx.x * blockDim.x + threadIdx.x) >> 5;
    int lane = threadIdx.x & 31;
    if (warp >= N_NODES) return;
    uint2 raw = *(const uint2*)&H[(size_t)warp * 128 + lane * 4];
    float2 h01 = __half22float2(*(const __half2*)&raw.x);
    float2 h23 = __half22float2(*(const __half2*)&raw.y);
    float4 s = *(const float4*)&a_src[lane * 4];
    float4 d = *(const float4*)&a_dst[lane * 4];
    float ps = h01.x * s.x + h01.y * s.y + h23.x * s.z + h23.y * s.w;
    float pd = h01.x * d.x + h01.y * d.y + h23.x * d.z + h23.y * d.w;
#pragma unroll
    for (int o = 16; o; o >>= 1) {
        ps += __shfl_xor_sync(0xffffffffu, ps, o);
        pd += __shfl_xor_sync(0xffffffffu, pd, o);
    }
    if (lane == 0) { g_as[warp] = ps; g_ad[warp] = pd; }
}

// ---------------- edge aggregation (warp per destination node) ---------------
__device__ __forceinline__ float lrelu(float x) {
    return x > 0.0f ? x : NEG_SLOPE * x;
}

__global__ __launch_bounds__(256) void agg_kernel(
    const __half* __restrict__ H, const float* __restrict__ bias,
    float* __restrict__ Out, int do_relu)
{
    int warp = (blockIdx.x * blockDim.x + threadIdx.x) >> 5;
    int lane = threadIdx.x & 31;
    if (warp >= N_NODES) return;
    int beg = g_rowptr[warp], end = g_rowptr[warp + 1];
    float ad = g_ad[warp];

    // single pass online softmax. FINITE sentinel (not -inf!) so that the
    // empty-lane merge computes exp(0)*0 = 0 instead of exp(nan).
    float m = NEG_BIG, s = 0.0f;
    for (int i = beg + lane; i < end; i += 32) {
        float l = lrelu(g_as[g_csrc[i]] + ad);
        float nm = fmaxf(m, l);
        s = s * __expf(m - nm) + __expf(l - nm);
        m = nm;
    }
#pragma unroll
    for (int o = 16; o; o >>= 1) {
        float mo = __shfl_xor_sync(0xffffffffu, m, o);
        float so = __shfl_xor_sync(0xffffffffu, s, o);
        float nm = fmaxf(m, mo);
        s = s * __expf(m - nm) + so * __expf(mo - nm);
        m = nm;
    }
    float inv = (end > beg) ? 1.0f / s : 0.0f;

    // weighted feature accumulation (fp16 rows), unroll x2 for MLP
    float4 acc0 = make_float4(0, 0, 0, 0);
    float4 acc1 = make_float4(0, 0, 0, 0);
    int i = beg;
    for (; i + 1 < end; i += 2) {
        int s0 = g_csrc[i], s1 = g_csrc[i + 1];
        float w0 = __expf(lrelu(g_as[s0] + ad) - m) * inv;
        float w1 = __expf(lrelu(g_as[s1] + ad) - m) * inv;
        uint2 r0 = *(const uint2*)&H[(size_t)s0 * 128 + lane * 4];
        uint2 r1 = *(const uint2*)&H[(size_t)s1 * 128 + lane * 4];
        float2 a01 = __half22float2(*(const __half2*)&r0.x);
        float2 a23 = __half22float2(*(const __half2*)&r0.y);
        float2 b01 = __half22float2(*(const __half2*)&r1.x);
        float2 b23 = __half22float2(*(const __half2*)&r1.y);
        acc0.x = fmaf(w0, a01.x, acc0.x); acc0.y = fmaf(w0, a01.y, acc0.y);
        acc0.z = fmaf(w0, a23.x, acc0.z); acc0.w = fmaf(w0, a23.y, acc0.w);
        acc1.x = fmaf(w1, b01.x, acc1.x); acc1.y = fmaf(w1, b01.y, acc1.y);
        acc1.z = fmaf(w1, b23.x, acc1.z); acc1.w = fmaf(w1, b23.y, acc1.w);
    }
    if (i < end) {
        int s0 = g_csrc[i];
        float w0 = __expf(lrelu(g_as[s0] + ad) - m) * inv;
        uint2 r0 = *(const uint2*)&H[(size_t)s0 * 128 + lane * 4];
        float2 a01 = __half22float2(*(const __half2*)&r0.x);
        float2 a23 = __half22float2(*(const __half2*)&r0.y);
        acc0.x = fmaf(w0, a01.x, acc0.x); acc0.y = fmaf(w0, a01.y, acc0.y);
        acc0.z = fmaf(w0, a23.x, acc0.z); acc0.w = fmaf(w0, a23.y, acc0.w);
    }
    float4 acc = make_float4(acc0.x + acc1.x, acc0.y + acc1.y,
                             acc0.z + acc1.z, acc0.w + acc1.w);
    float4 bv = *(const float4*)&bias[lane * 4];
    acc.x += bv.x; acc.y += bv.y; acc.z += bv.z; acc.w += bv.w;
    if (do_relu) {
        acc.x = fmaxf(acc.x, 0.0f); acc.y = fmaxf(acc.y, 0.0f);
        acc.z = fmaxf(acc.z, 0.0f); acc.w = fmaxf(acc.w, 0.0f);
    }
    *(float4*)&Out[(size_t)warp * 128 + lane * 4] = acc;
}

// ---------------- pooling (batch is sorted -> run-length segmented) ----------
#define NODES_PER_BLOCK 64
__global__ void pool_kernel(const float* __restrict__ H, const void* __restrict__ batchbuf) {
    int tid = threadIdx.x;   // 128 = channel
    int n0 = blockIdx.x * NODES_PER_BLOCK;
    if (n0 >= N_NODES) return;
    int n1 = min(n0 + NODES_PER_BLOCK, N_NODES);
    int is64 = g_is64;
    const long long* b64 = (const long long*)batchbuf;
    const int* b32 = (const int*)batchbuf;
    int cur = is64 ? (int)b64[n0] : b32[n0];
    float acc = 0.0f;
    int run = 0;
    for (int n = n0; n < n1; n++) {
        int gg = is64 ? (int)b64[n] : b32[n];
        if (gg != cur) {
            atomicAdd(&g_pool[cur * 128 + tid], acc);
            if (tid == 0) atomicAdd(&g_cnt[cur], run);
            acc = 0.0f; run = 0; cur = gg;
        }
        acc += H[(size_t)n * 128 + tid];
        run++;
    }
    atomicAdd(&g_pool[cur * 128 + tid], acc);
    if (tid == 0) atomicAdd(&g_cnt[cur], run);
}

// ---------------- final linear ----------------------------------------------
__global__ void final_kernel(const float* __restrict__ lin_w,
                             const float* __restrict__ lin_b,
                             float* __restrict__ out)
{
    int t = blockIdx.x * blockDim.x + threadIdx.x;
    if (t >= N_GRAPHS * OUT_F) return;
    int gg = t >> 3, o = t & 7;
    float cval = fmaxf((float)g_cnt[gg], 1.0f);
    float invc = 1.0f / cval;
    float acc = 0.0f;
    for (int k = 0; k < 128; k++)
        acc = fmaf(g_pool[gg * 128 + k] * invc, lin_w[k * OUT_F + o], acc);
    out[t] = acc + lin_b[o];
}

// ---------------- driver -----------------------------------------------------
extern "C" void kernel_launch(void* const* d_in, const int* in_sizes, int n_in,
                              void* d_out, int out_size)
{
    const float* x      = (const float*)d_in[0];
    const void*  eidx   = d_in[1];
    const void*  batch  = d_in[3];
    const float* W[3]     = {(const float*)d_in[4],  (const float*)d_in[8],  (const float*)d_in[12]};
    const float* a_src[3] = {(const float*)d_in[5],  (const float*)d_in[9],  (const float*)d_in[13]};
    const float* a_dst[3] = {(const float*)d_in[6],  (const float*)d_in[10], (const float*)d_in[14]};
    const float* bias[3]  = {(const float*)d_in[7],  (const float*)d_in[11], (const float*)d_in[15]};
    const float* lin_w  = (const float*)d_in[16];
    const float* lin_b  = (const float*)d_in[17];
    float* out = (float*)d_out;

    const int E = N_EDGES;
    const int eb = (E + 255) / 256;
    const int nb = (N_NODES + 255) / 256;

    int* degp; cudaGetSymbolAddress((void**)&degp, g_deg);
    __half* hbuf; cudaGetSymbolAddress((void**)&hbuf, g_h);
    float* obuf;  cudaGetSymbolAddress((void**)&obuf, g_out);

    // dtype detection + index conversion + degree histogram
    detect_kernel<<<1, 256>>>((const unsigned*)eidx);
    zero_i<<<nb, 256>>>(degp, N_NODES);
    convert_edges<<<eb, 256>>>(eidx, E);

    // CSR by destination (hierarchical scan)
    scan1_kernel<<<N_SCAN_BLOCKS, 1024>>>();
    scan2_kernel<<<1, 64>>>();
    scan3_kernel<<<nb, 256>>>();
    scatter_kernel<<<eb, 256>>>(E);

    const int gemm_blocks = (N_NODES + BM - 1) / BM;
    const int warp_blocks = (N_NODES * 32 + 255) / 256;

    // layer 0 (input x, K=256)
    gemm_tf32_kernel<<<gemm_blocks, 256>>>(x, W[0], hbuf, N_NODES, IN_F);
    alpha_kernel<<<warp_blocks, 256>>>(hbuf, a_src[0], a_dst[0]);
    agg_kernel<<<warp_blocks, 256>>>(hbuf, bias[0], obuf, 1);

    // layers 1,2 (K=128)
    for (int l = 1; l < 3; l++) {
        gemm_tf32_kernel<<<gemm_blocks, 256>>>(obuf, W[l], hbuf, N_NODES, HID);
        alpha_kernel<<<warp_blocks, 256>>>(hbuf, a_src[l], a_dst[l]);
        agg_kernel<<<warp_blocks, 256>>>(hbuf, bias[l], obuf, l == 2 ? 0 : 1);
    }

    // pooling + final linear
    zero_pool_kernel<<<(N_GRAPHS * HID + 255) / 256, 256>>>();
    pool_kernel<<<(N_NODES + NODES_PER_BLOCK - 1) / NODES_PER_BLOCK, 128>>>(obuf, batch);
    final_kernel<<<(N_GRAPHS * OUT_F + 255) / 256, 256>>>(lin_w, lin_b, out);
}